// round 14
// baseline (speedup 1.0000x reference)
#include <cuda_runtime.h>
#include <cstdint>

// SSIM loss, NCHW (32,3,512,512) fp32, 3x3 box, reflect pad 1, scalar mean.
// R13: R9 skeleton (best: float4 loads, RPB32, rolled loop, distance-2 ring,
// ~80 regs @ 6 blocks/SM) with the halo exchange moved OFF the emit critical
// path: raw edge scalars shuffled at LOAD time (4 SHFL/row vs 10 in emit),
// packed as edge pairs whose vertical sums replace the wasted scalar halo ops
// one-for-one. Register-neutral via the constant diet (tail folded into fp64
// finalize, 2A = A+A).

#define H 512
#define W 512
#define PLANES (32 * 3)
#define RPB 32
#define BLOCKS_X (H / RPB)           // 16
#define NBLOCKS (BLOCKS_X * PLANES)  // 1536

typedef unsigned long long u64;

__device__ float g_partials[NBLOCKS];
__device__ unsigned int g_count = 0;

__device__ __forceinline__ u64 pk(float lo, float hi) {
    u64 r; asm("mov.b64 %0, {%1, %2};" : "=l"(r) : "f"(lo), "f"(hi)); return r;
}
__device__ __forceinline__ void unpk(u64 v, float& lo, float& hi) {
    asm("mov.b64 {%0, %1}, %2;" : "=f"(lo), "=f"(hi) : "l"(v));
}
__device__ __forceinline__ float lo64(u64 v) {
    float f; asm("{\n\t.reg .f32 t;\n\tmov.b64 {%0, t}, %1;\n\t}" : "=f"(f) : "l"(v)); return f;
}
__device__ __forceinline__ float hi64(u64 v) {
    float f; asm("{\n\t.reg .f32 t;\n\tmov.b64 {t, %0}, %1;\n\t}" : "=f"(f) : "l"(v)); return f;
}
__device__ __forceinline__ u64 add2(u64 a, u64 b) {
    u64 d; asm("add.rn.f32x2 %0, %1, %2;" : "=l"(d) : "l"(a), "l"(b)); return d;
}
__device__ __forceinline__ u64 sub2(u64 a, u64 b) {
    u64 d; asm("sub.rn.f32x2 %0, %1, %2;" : "=l"(d) : "l"(a), "l"(b)); return d;
}
__device__ __forceinline__ u64 mul2(u64 a, u64 b) {
    u64 d; asm("mul.rn.f32x2 %0, %1, %2;" : "=l"(d) : "l"(a), "l"(b)); return d;
}
__device__ __forceinline__ u64 fma2(u64 a, u64 b, u64 c) {
    u64 d; asm("fma.rn.f32x2 %0, %1, %2, %3;" : "=l"(d) : "l"(a), "l"(b), "l"(c)); return d;
}
__device__ __forceinline__ float rcpf(float x) {
    float r; asm("rcp.approx.ftz.f32 %0, %1;" : "=f"(r) : "f"(x)); return r;
}

// Branch-free reflect for in-loop indices i in [2, 2H-2]
__device__ __forceinline__ int refl_hi(int i) {
    return min(i, 2 * (H - 1) - i);
}

// Row: packed x,y pairs for 4 columns + packed edge pairs E=(col c-1, col c+4).
struct RowR { u64 X0, X1, Y0, Y1, Ex, Ey; };

struct K { u64 p18, p9, c1p, c2p; };

__device__ __forceinline__ void load_row(RowR& R,
                                         const float* __restrict__ xp,
                                         const float* __restrict__ yp,
                                         int rr, int base, int hcol, bool doHalo,
                                         int lane, int wseg) {
    const float4 xv = *reinterpret_cast<const float4*>(xp + rr * W + base);
    const float4 yv = *reinterpret_cast<const float4*>(yp + rr * W + base);
    R.X0 = pk(xv.x, xv.y); R.X1 = pk(xv.z, xv.w);
    R.Y0 = pk(yv.x, yv.y); R.Y1 = pk(yv.z, yv.w);

    // halo scalar for warp-boundary lanes (one predicated LDG per image)
    float hx = 0.0f, hy = 0.0f;
    if (doHalo) {
        hx = __ldg(xp + rr * W + hcol);
        hy = __ldg(yp + rr * W + hcol);
    }
    // raw edge values via intra-warp shuffle (load path, hidden by ring distance)
    float xL = __shfl_up_sync(0xffffffffu, xv.w, 1);
    float xR = __shfl_down_sync(0xffffffffu, xv.x, 1);
    float yL = __shfl_up_sync(0xffffffffu, yv.w, 1);
    float yR = __shfl_down_sync(0xffffffffu, yv.x, 1);
    if (lane == 0)  { xL = (wseg == 0) ? xv.y : hx;  yL = (wseg == 0) ? yv.y : hy; }
    if (lane == 31) { xR = (wseg == 3) ? xv.z : hx;  yR = (wseg == 3) ? yv.z : hy; }
    R.Ex = pk(xL, xR);
    R.Ey = pk(yL, yR);
}

// q = n/d on raw 3x3 window sums (packed pixel pair); /9 factors cancel:
//   n/d = (2A+81C1)(18 Sxy - 2A + 81C2) / ((B+C+81C1)(9(Sxx+Syy)-B-C+81C2))
// 2A built as A+A (no +/-2 constant regs). Affine tail (0.5 - q/2) and clip
// folded into the fp64 finalize (clip is ulp-level only; tolerance 1e-3).
__device__ __forceinline__ u64 ssim_q(u64 Sx, u64 Sy, u64 Sxx, u64 Syy, u64 Sxy,
                                      const K& k) {
    u64 A  = mul2(Sx, Sy);
    u64 B  = mul2(Sx, Sx);
    u64 C  = mul2(Sy, Sy);
    u64 A2 = add2(A, A);
    u64 n1 = add2(A2, k.c1p);
    u64 t  = sub2(k.c2p, A2);
    u64 n2 = fma2(Sxy, k.p18, t);
    u64 n  = mul2(n1, n2);
    u64 BC = add2(B, C);
    u64 d1 = add2(BC, k.c1p);
    u64 u  = sub2(k.c2p, BC);
    u64 d2 = fma2(add2(Sxx, Syy), k.p9, u);
    u64 d  = mul2(d1, d2);
    float dd0, dd1; unpk(d, dd0, dd1);
    u64 rp = pk(rcpf(dd0), rcpf(dd1));
    return mul2(n, rp);
}

// Horizontal packed 3-sum; lv/rv come from the packed edge vertical sum vE
// (no SHFL, no lane predicates — pure register math).
#define HQ(q)                                                                 \
    float a0_##q, a1_##q, a2_##q, a3_##q;                                     \
    unpk(v0_##q, a0_##q, a1_##q);                                             \
    unpk(v1_##q, a2_##q, a3_##q);                                             \
    u64 mid_##q = pk(a1_##q, a2_##q);                                         \
    u64 h0_##q = add2(add2(pk(lo64(vE_##q), a0_##q), v0_##q), mid_##q);       \
    u64 h1_##q = add2(add2(mid_##q, v1_##q), pk(a3_##q, hi64(vE_##q)));

__device__ __forceinline__ void emit(const RowR& A, const RowR& B, const RowR& C,
                                     u64& acc, const K& k) {
    // vertical 3-sums; squares/products as FMA chains
    u64 v0_X  = add2(add2(A.X0, B.X0), C.X0);
    u64 v1_X  = add2(add2(A.X1, B.X1), C.X1);
    u64 v0_Y  = add2(add2(A.Y0, B.Y0), C.Y0);
    u64 v1_Y  = add2(add2(A.Y1, B.Y1), C.Y1);
    u64 v0_XX = fma2(A.X0, A.X0, fma2(B.X0, B.X0, mul2(C.X0, C.X0)));
    u64 v1_XX = fma2(A.X1, A.X1, fma2(B.X1, B.X1, mul2(C.X1, C.X1)));
    u64 v0_YY = fma2(A.Y0, A.Y0, fma2(B.Y0, B.Y0, mul2(C.Y0, C.Y0)));
    u64 v1_YY = fma2(A.Y1, A.Y1, fma2(B.Y1, B.Y1, mul2(C.Y1, C.Y1)));
    u64 v0_XY = fma2(A.X0, A.Y0, fma2(B.X0, B.Y0, mul2(C.X0, C.Y0)));
    u64 v1_XY = fma2(A.X1, A.Y1, fma2(B.X1, B.Y1, mul2(C.X1, C.Y1)));
    // packed edge vertical sums (both halves used: left col & right col)
    u64 vE_X  = add2(add2(A.Ex, B.Ex), C.Ex);
    u64 vE_Y  = add2(add2(A.Ey, B.Ey), C.Ey);
    u64 vE_XX = fma2(A.Ex, A.Ex, fma2(B.Ex, B.Ex, mul2(C.Ex, C.Ex)));
    u64 vE_YY = fma2(A.Ey, A.Ey, fma2(B.Ey, B.Ey, mul2(C.Ey, C.Ey)));
    u64 vE_XY = fma2(A.Ex, A.Ey, fma2(B.Ex, B.Ey, mul2(C.Ex, C.Ey)));

    HQ(X) HQ(Y) HQ(XX) HQ(YY) HQ(XY)
    acc = add2(acc, ssim_q(h0_X, h0_Y, h0_XX, h0_YY, h0_XY, k));
    acc = add2(acc, ssim_q(h1_X, h1_Y, h1_XX, h1_YY, h1_XY, k));
}

__global__ __launch_bounds__(128, 6)
void ssim_main(const float* __restrict__ x, const float* __restrict__ y,
               float* __restrict__ out) {
    const int tid   = threadIdx.x;
    const int lane  = tid & 31;
    const int wseg  = tid >> 5;                 // 0..3, 128-col segment
    const int plane = blockIdx.y;
    const int r0    = blockIdx.x * RPB;

    const int segbase = wseg * 128;
    const int base    = segbase + lane * 4;
    const float* __restrict__ xp = x + (size_t)plane * H * W;
    const float* __restrict__ yp = y + (size_t)plane * H * W;

    const int  hcol   = (lane == 0) ? ((wseg == 0) ? 1 : segbase - 1)
                                    : ((wseg == 3) ? 510 : segbase + 128);
    const bool doHalo = (lane == 0) || (lane == 31);

    K k;
    k.p18 = pk(18.0f, 18.0f);
    k.p9  = pk(9.0f, 9.0f);
    k.c1p = pk(0.0081f, 0.0081f);   // 81*C1
    k.c2p = pk(0.0729f, 0.0729f);   // 81*C2

    // ---- pipelined 4-buffer ring: load row r+2 before emitting row r ----
    RowR b0, b1, b2, b3;
    load_row(b0, xp, yp, (r0 == 0) ? 1 : (r0 - 1), base, hcol, doHalo, lane, wseg);
    load_row(b1, xp, yp, r0,     base, hcol, doHalo, lane, wseg);
    load_row(b2, xp, yp, r0 + 1, base, hcol, doHalo, lane, wseg);

    u64 acc0 = pk(0.0f, 0.0f), acc1 = pk(0.0f, 0.0f);
    #pragma unroll 1   // rolled: hot body fits L1.5 I$ (R9 finding)
    for (int j = 0; j < RPB; j += 4) {
        const int rr = r0 + j;
        load_row(b3, xp, yp, refl_hi(rr + 2), base, hcol, doHalo, lane, wseg);
        emit(b0, b1, b2, acc0, k);                 // row rr
        load_row(b0, xp, yp, refl_hi(rr + 3), base, hcol, doHalo, lane, wseg);
        emit(b1, b2, b3, acc1, k);                 // row rr+1
        load_row(b1, xp, yp, refl_hi(rr + 4), base, hcol, doHalo, lane, wseg);
        emit(b2, b3, b0, acc0, k);                 // row rr+2
        load_row(b2, xp, yp, refl_hi(rr + 5), base, hcol, doHalo, lane, wseg);
        emit(b3, b0, b1, acc1, k);                 // row rr+3
    }

    // ---- block reduction (sum of q values) ----
    u64 acc = add2(acc0, acc1);
    float alo, ahi; unpk(acc, alo, ahi);
    float accf = alo + ahi;
    #pragma unroll
    for (int o = 16; o > 0; o >>= 1)
        accf += __shfl_xor_sync(0xffffffffu, accf, o);

    __shared__ float wsum[4];
    __shared__ int   last_flag;
    if (lane == 0) wsum[wseg] = accf;
    __syncthreads();

    if (tid == 0) {
        float p = wsum[0] + wsum[1] + wsum[2] + wsum[3];
        g_partials[blockIdx.y * gridDim.x + blockIdx.x] = p;
        __threadfence();
        unsigned t = atomicAdd(&g_count, 1u);
        last_flag = (t == NBLOCKS - 1);
    }
    __syncthreads();

    if (last_flag) {
        double s = 0.0;
        for (int i = tid; i < NBLOCKS; i += 128)
            s += (double)__ldcg(&g_partials[i]);
        #pragma unroll
        for (int o = 16; o > 0; o >>= 1)
            s += __shfl_xor_sync(0xffffffffu, s, o);
        __shared__ double dsum[4];
        if (lane == 0) dsum[wseg] = s;
        __syncthreads();
        if (tid == 0) {
            // mean of (1 - q)/2 = 0.5 - (sum q)/(2N)
            double total = dsum[0] + dsum[1] + dsum[2] + dsum[3];
            const double N = (double)PLANES * H * W;
            out[0] = (float)(0.5 - total / (2.0 * N));
            g_count = 0;  // reset for next graph replay
        }
    }
}

extern "C" void kernel_launch(void* const* d_in, const int* in_sizes, int n_in,
                              void* d_out, int out_size) {
    const float* x = (const float*)d_in[0];
    const float* y = (const float*)d_in[1];
    float* out = (float*)d_out;

    dim3 grid(BLOCKS_X, PLANES);
    ssim_main<<<grid, 128>>>(x, y, out);
}

// round 15
// speedup vs baseline: 1.0473x; 1.0473x over previous
#include <cuda_runtime.h>
#include <cstdint>

// SSIM loss, NCHW (32,3,512,512) fp32, 3x3 box, reflect pad 1, scalar mean.
// R14: R9 skeleton (best, 59.9us) with pointer-increment addressing on the
// 15/16 blocks that can never touch a reflected row: in-loop loads become
// LDG [ptr + const*W] with compile-time immediates, pointers advance once per
// 4 rows (kills the per-load refl/min + IMAD alu chain). Last block keeps the
// exact R9 refl path. Register-neutral via the R12 constant diet (affine tail
// folded into fp64 finalize, 2A = A+A). Emit/shuffle machinery identical to R9.

#define H 512
#define W 512
#define PLANES (32 * 3)
#define RPB 32
#define BLOCKS_X (H / RPB)           // 16
#define NBLOCKS (BLOCKS_X * PLANES)  // 1536

typedef unsigned long long u64;

__device__ float g_partials[NBLOCKS];
__device__ unsigned int g_count = 0;

__device__ __forceinline__ u64 pk(float lo, float hi) {
    u64 r; asm("mov.b64 %0, {%1, %2};" : "=l"(r) : "f"(lo), "f"(hi)); return r;
}
__device__ __forceinline__ void unpk(u64 v, float& lo, float& hi) {
    asm("mov.b64 {%0, %1}, %2;" : "=f"(lo), "=f"(hi) : "l"(v));
}
__device__ __forceinline__ u64 add2(u64 a, u64 b) {
    u64 d; asm("add.rn.f32x2 %0, %1, %2;" : "=l"(d) : "l"(a), "l"(b)); return d;
}
__device__ __forceinline__ u64 sub2(u64 a, u64 b) {
    u64 d; asm("sub.rn.f32x2 %0, %1, %2;" : "=l"(d) : "l"(a), "l"(b)); return d;
}
__device__ __forceinline__ u64 mul2(u64 a, u64 b) {
    u64 d; asm("mul.rn.f32x2 %0, %1, %2;" : "=l"(d) : "l"(a), "l"(b)); return d;
}
__device__ __forceinline__ u64 fma2(u64 a, u64 b, u64 c) {
    u64 d; asm("fma.rn.f32x2 %0, %1, %2, %3;" : "=l"(d) : "l"(a), "l"(b), "l"(c)); return d;
}
__device__ __forceinline__ float rcpf(float x) {
    float r; asm("rcp.approx.ftz.f32 %0, %1;" : "=f"(r) : "f"(x)); return r;
}

// Branch-free reflect for in-loop indices i in [2, 2H-2]
__device__ __forceinline__ int refl_hi(int i) {
    return min(i, 2 * (H - 1) - i);
}

// Raw row: packed x,y for 4 columns + halo scalars (lanes 0/31 only).
struct RowR { u64 X0, X1, Y0, Y1; float hX, hY; };

struct K { u64 p18, p9, c1p, c2p; };

// indexed load (prologue + edge-block path)
__device__ __forceinline__ void load_row(RowR& R,
                                         const float* __restrict__ xp,
                                         const float* __restrict__ yp,
                                         int rr, int base, int hcol, bool doHalo) {
    const float4 xv = *reinterpret_cast<const float4*>(xp + rr * W + base);
    const float4 yv = *reinterpret_cast<const float4*>(yp + rr * W + base);
    R.X0 = pk(xv.x, xv.y); R.X1 = pk(xv.z, xv.w);
    R.Y0 = pk(yv.x, yv.y); R.Y1 = pk(yv.z, yv.w);
    if (doHalo) {
        R.hX = __ldg(xp + rr * W + hcol);
        R.hY = __ldg(yp + rr * W + hcol);
    }
}

// pointer+immediate load (interior fast path): address = ptr + ROFF*W,
// ROFF is a compile-time constant folded into the LDG immediate.
template<int ROFF>
__device__ __forceinline__ void load_row_p(RowR& R,
                                           const float* __restrict__ px,
                                           const float* __restrict__ py,
                                           const float* __restrict__ hpx,
                                           const float* __restrict__ hpy,
                                           bool doHalo) {
    const float4 xv = *reinterpret_cast<const float4*>(px + ROFF * W);
    const float4 yv = *reinterpret_cast<const float4*>(py + ROFF * W);
    R.X0 = pk(xv.x, xv.y); R.X1 = pk(xv.z, xv.w);
    R.Y0 = pk(yv.x, yv.y); R.Y1 = pk(yv.z, yv.w);
    if (doHalo) {
        R.hX = __ldg(hpx + ROFF * W);
        R.hY = __ldg(hpy + ROFF * W);
    }
}

// q = n/d on raw 3x3 window sums (packed pixel pair); /9 factors cancel:
//   n/d = (2A+81C1)(18 Sxy - 2A + 81C2) / ((B+C+81C1)(9(Sxx+Syy)-B-C+81C2))
// 2A built as A+A (no +/-2 constant regs). Affine tail (0.5 - q/2) and clip
// folded into the fp64 finalize (clip is ulp-level only; tolerance 1e-3).
__device__ __forceinline__ u64 ssim_q(u64 Sx, u64 Sy, u64 Sxx, u64 Syy, u64 Sxy,
                                      const K& k) {
    u64 A  = mul2(Sx, Sy);
    u64 B  = mul2(Sx, Sx);
    u64 C  = mul2(Sy, Sy);
    u64 A2 = add2(A, A);
    u64 n1 = add2(A2, k.c1p);
    u64 t  = sub2(k.c2p, A2);
    u64 n2 = fma2(Sxy, k.p18, t);
    u64 n  = mul2(n1, n2);
    u64 BC = add2(B, C);
    u64 d1 = add2(BC, k.c1p);
    u64 u  = sub2(k.c2p, BC);
    u64 d2 = fma2(add2(Sxx, Syy), k.p9, u);
    u64 d  = mul2(d1, d2);
    float dd0, dd1; unpk(d, dd0, dd1);
    u64 rp = pk(rcpf(dd0), rcpf(dd1));
    return mul2(n, rp);
}

// Horizontal packed 3-sum of vertical sums v0 (px 0,1), v1 (px 2,3), halo hv.
// (emit-time shuffles: the known-good placement — R13 proved load-time fails)
#define HQ(q)                                                                 \
    float a0_##q, a1_##q, a2_##q, a3_##q;                                     \
    unpk(v0_##q, a0_##q, a1_##q);                                             \
    unpk(v1_##q, a2_##q, a3_##q);                                             \
    float lv_##q = __shfl_up_sync(0xffffffffu, a3_##q, 1);                    \
    float rv_##q = __shfl_down_sync(0xffffffffu, a0_##q, 1);                  \
    if (lane == 0)  lv_##q = (wseg == 0) ? a1_##q : hv_##q;                   \
    if (lane == 31) rv_##q = (wseg == 3) ? a2_##q : hv_##q;                   \
    u64 mid_##q = pk(a1_##q, a2_##q);                                         \
    u64 h0_##q = add2(add2(pk(lv_##q, a0_##q), v0_##q), mid_##q);             \
    u64 h1_##q = add2(add2(mid_##q, v1_##q), pk(a3_##q, rv_##q));

__device__ __forceinline__ void emit(const RowR& A, const RowR& B, const RowR& C,
                                     u64& acc, int lane, int wseg, const K& k) {
    u64 v0_X  = add2(add2(A.X0, B.X0), C.X0);
    u64 v1_X  = add2(add2(A.X1, B.X1), C.X1);
    u64 v0_Y  = add2(add2(A.Y0, B.Y0), C.Y0);
    u64 v1_Y  = add2(add2(A.Y1, B.Y1), C.Y1);
    u64 v0_XX = fma2(A.X0, A.X0, fma2(B.X0, B.X0, mul2(C.X0, C.X0)));
    u64 v1_XX = fma2(A.X1, A.X1, fma2(B.X1, B.X1, mul2(C.X1, C.X1)));
    u64 v0_YY = fma2(A.Y0, A.Y0, fma2(B.Y0, B.Y0, mul2(C.Y0, C.Y0)));
    u64 v1_YY = fma2(A.Y1, A.Y1, fma2(B.Y1, B.Y1, mul2(C.Y1, C.Y1)));
    u64 v0_XY = fma2(A.X0, A.Y0, fma2(B.X0, B.Y0, mul2(C.X0, C.Y0)));
    u64 v1_XY = fma2(A.X1, A.Y1, fma2(B.X1, B.Y1, mul2(C.X1, C.Y1)));

    float hv_X  = A.hX + B.hX + C.hX;
    float hv_Y  = A.hY + B.hY + C.hY;
    float hv_XX = fmaf(A.hX, A.hX, fmaf(B.hX, B.hX, C.hX * C.hX));
    float hv_YY = fmaf(A.hY, A.hY, fmaf(B.hY, B.hY, C.hY * C.hY));
    float hv_XY = fmaf(A.hX, A.hY, fmaf(B.hX, B.hY, C.hX * C.hY));

    HQ(X) HQ(Y) HQ(XX) HQ(YY) HQ(XY)
    acc = add2(acc, ssim_q(h0_X, h0_Y, h0_XX, h0_YY, h0_XY, k));
    acc = add2(acc, ssim_q(h1_X, h1_Y, h1_XX, h1_YY, h1_XY, k));
}

__global__ __launch_bounds__(128, 6)
void ssim_main(const float* __restrict__ x, const float* __restrict__ y,
               float* __restrict__ out) {
    const int tid   = threadIdx.x;
    const int lane  = tid & 31;
    const int wseg  = tid >> 5;                 // 0..3, 128-col segment
    const int plane = blockIdx.y;
    const int r0    = blockIdx.x * RPB;

    const int segbase = wseg * 128;
    const int base    = segbase + lane * 4;
    const float* __restrict__ xp = x + (size_t)plane * H * W;
    const float* __restrict__ yp = y + (size_t)plane * H * W;

    const int  hcol   = (lane == 0) ? ((wseg == 0) ? 1 : segbase - 1)
                                    : ((wseg == 3) ? 510 : segbase + 128);
    const bool doHalo = (lane == 0) || (lane == 31);

    K k;
    k.p18 = pk(18.0f, 18.0f);
    k.p9  = pk(9.0f, 9.0f);
    k.c1p = pk(0.0081f, 0.0081f);   // 81*C1
    k.c2p = pk(0.0729f, 0.0729f);   // 81*C2

    // ---- prologue: rows r0-1, r0, r0+1 (lower reflect only possible here)
    RowR b0, b1, b2, b3;
    load_row(b0, xp, yp, (r0 == 0) ? 1 : (r0 - 1), base, hcol, doHalo);
    load_row(b1, xp, yp, r0,     base, hcol, doHalo);
    load_row(b2, xp, yp, r0 + 1, base, hcol, doHalo);

    u64 acc0 = pk(0.0f, 0.0f), acc1 = pk(0.0f, 0.0f);

    if (blockIdx.x != BLOCKS_X - 1) {
        // ---- interior fast path: rows r0+2 .. r0+33 all < H, no reflection.
        // Loads are LDG [ptr + const*W]; pointers advance once per 4 rows.
        const float* px  = xp + (r0 + 2) * W + base;
        const float* py  = yp + (r0 + 2) * W + base;
        const float* hpx = xp + (r0 + 2) * W + hcol;
        const float* hpy = yp + (r0 + 2) * W + hcol;
        #pragma unroll 1   // rolled: fits L1.5 I$ (R9 finding)
        for (int j = 0; j < RPB; j += 4) {
            load_row_p<0>(b3, px, py, hpx, hpy, doHalo);
            emit(b0, b1, b2, acc0, lane, wseg, k);
            load_row_p<1>(b0, px, py, hpx, hpy, doHalo);
            emit(b1, b2, b3, acc1, lane, wseg, k);
            load_row_p<2>(b1, px, py, hpx, hpy, doHalo);
            emit(b2, b3, b0, acc0, lane, wseg, k);
            load_row_p<3>(b2, px, py, hpx, hpy, doHalo);
            emit(b3, b0, b1, acc1, lane, wseg, k);
            px += 4 * W; py += 4 * W; hpx += 4 * W; hpy += 4 * W;
        }
    } else {
        // ---- edge path (last row-block): exact R9 refl loop
        #pragma unroll 1
        for (int j = 0; j < RPB; j += 4) {
            const int rr = r0 + j;
            load_row(b3, xp, yp, refl_hi(rr + 2), base, hcol, doHalo);
            emit(b0, b1, b2, acc0, lane, wseg, k);
            load_row(b0, xp, yp, refl_hi(rr + 3), base, hcol, doHalo);
            emit(b1, b2, b3, acc1, lane, wseg, k);
            load_row(b1, xp, yp, refl_hi(rr + 4), base, hcol, doHalo);
            emit(b2, b3, b0, acc0, lane, wseg, k);
            load_row(b2, xp, yp, refl_hi(rr + 5), base, hcol, doHalo);
            emit(b3, b0, b1, acc1, lane, wseg, k);
        }
    }

    // ---- block reduction (sum of q values) ----
    u64 acc = add2(acc0, acc1);
    float alo, ahi; unpk(acc, alo, ahi);
    float accf = alo + ahi;
    #pragma unroll
    for (int o = 16; o > 0; o >>= 1)
        accf += __shfl_xor_sync(0xffffffffu, accf, o);

    __shared__ float wsum[4];
    __shared__ int   last_flag;
    if (lane == 0) wsum[wseg] = accf;
    __syncthreads();

    if (tid == 0) {
        float p = wsum[0] + wsum[1] + wsum[2] + wsum[3];
        g_partials[blockIdx.y * gridDim.x + blockIdx.x] = p;
        __threadfence();
        unsigned t = atomicAdd(&g_count, 1u);
        last_flag = (t == NBLOCKS - 1);
    }
    __syncthreads();

    if (last_flag) {
        double s = 0.0;
        for (int i = tid; i < NBLOCKS; i += 128)
            s += (double)__ldcg(&g_partials[i]);
        #pragma unroll
        for (int o = 16; o > 0; o >>= 1)
            s += __shfl_xor_sync(0xffffffffu, s, o);
        __shared__ double dsum[4];
        if (lane == 0) dsum[wseg] = s;
        __syncthreads();
        if (tid == 0) {
            // mean of (1 - q)/2 = 0.5 - (sum q)/(2N)
            double total = dsum[0] + dsum[1] + dsum[2] + dsum[3];
            const double N = (double)PLANES * H * W;
            out[0] = (float)(0.5 - total / (2.0 * N));
            g_count = 0;  // reset for next graph replay
        }
    }
}

extern "C" void kernel_launch(void* const* d_in, const int* in_sizes, int n_in,
                              void* d_out, int out_size) {
    const float* x = (const float*)d_in[0];
    const float* y = (const float*)d_in[1];
    float* out = (float*)d_out;

    dim3 grid(BLOCKS_X, PLANES);
    ssim_main<<<grid, 128>>>(x, y, out);
}

// round 16
// speedup vs baseline: 1.2254x; 1.1701x over previous
#include <cuda_runtime.h>
#include <cstdint>

// SSIM loss, NCHW (32,3,512,512) fp32, 3x3 box, reflect pad 1, scalar mean.
// R15: byte-identical to R9 (best, 59.9us) except RPB 32 -> 8. 6144 blocks
// over 888 residency slots = 6.92 rounds -> scheduler drain tail drops from
// 13.5% (ceil(1.73)=2) to 1.2% (ceil(6.92)=7). Single-variable experiment.

#define H 512
#define W 512
#define PLANES (32 * 3)
#define RPB 8
#define BLOCKS_X (H / RPB)           // 64
#define NBLOCKS (BLOCKS_X * PLANES)  // 6144

typedef unsigned long long u64;

__device__ float g_partials[NBLOCKS];
__device__ unsigned int g_count = 0;

__device__ __forceinline__ u64 pk(float lo, float hi) {
    u64 r; asm("mov.b64 %0, {%1, %2};" : "=l"(r) : "f"(lo), "f"(hi)); return r;
}
__device__ __forceinline__ void unpk(u64 v, float& lo, float& hi) {
    asm("mov.b64 {%0, %1}, %2;" : "=f"(lo), "=f"(hi) : "l"(v));
}
__device__ __forceinline__ u64 add2(u64 a, u64 b) {
    u64 d; asm("add.rn.f32x2 %0, %1, %2;" : "=l"(d) : "l"(a), "l"(b)); return d;
}
__device__ __forceinline__ u64 sub2(u64 a, u64 b) {
    u64 d; asm("sub.rn.f32x2 %0, %1, %2;" : "=l"(d) : "l"(a), "l"(b)); return d;
}
__device__ __forceinline__ u64 mul2(u64 a, u64 b) {
    u64 d; asm("mul.rn.f32x2 %0, %1, %2;" : "=l"(d) : "l"(a), "l"(b)); return d;
}
__device__ __forceinline__ u64 fma2(u64 a, u64 b, u64 c) {
    u64 d; asm("fma.rn.f32x2 %0, %1, %2, %3;" : "=l"(d) : "l"(a), "l"(b), "l"(c)); return d;
}
__device__ __forceinline__ float rcpf(float x) {
    float r; asm("rcp.approx.ftz.f32 %0, %1;" : "=f"(r) : "f"(x)); return r;
}

// Branch-free reflect for in-loop indices i in [2, 2H-2]
__device__ __forceinline__ int refl_hi(int i) {
    return min(i, 2 * (H - 1) - i);
}

// Raw row: packed x,y for 4 columns + halo scalars (lanes 0/31 only).
struct RowR { u64 X0, X1, Y0, Y1; float hX, hY; };

struct K { u64 twop, n2p, p18, p9, c1p, c2p, nhp, php; };

__device__ __forceinline__ void load_row(RowR& R,
                                         const float* __restrict__ xp,
                                         const float* __restrict__ yp,
                                         int rr, int base, int hcol, bool doHalo) {
    const float4 xv = *reinterpret_cast<const float4*>(xp + rr * W + base);
    const float4 yv = *reinterpret_cast<const float4*>(yp + rr * W + base);
    R.X0 = pk(xv.x, xv.y); R.X1 = pk(xv.z, xv.w);
    R.Y0 = pk(yv.x, yv.y); R.Y1 = pk(yv.z, yv.w);
    if (doHalo) {
        R.hX = __ldg(xp + rr * W + hcol);
        R.hY = __ldg(yp + rr * W + hcol);
    }
}

// SSIM on raw 3x3 window sums (packed pixel pair); /9 factors cancel:
//   n/d = (2A+81C1)(18 Sxy - 2A + 81C2) / ((B+C+81C1)(9(Sxx+Syy)-B-C+81C2))
__device__ __forceinline__ u64 ssim2(u64 Sx, u64 Sy, u64 Sxx, u64 Syy, u64 Sxy,
                                     const K& k) {
    u64 A  = mul2(Sx, Sy);
    u64 B  = mul2(Sx, Sx);
    u64 C  = mul2(Sy, Sy);
    u64 n1 = fma2(A, k.twop, k.c1p);
    u64 t  = fma2(A, k.n2p,  k.c2p);
    u64 n2 = fma2(Sxy, k.p18, t);
    u64 n  = mul2(n1, n2);
    u64 BC = add2(B, C);
    u64 d1 = add2(BC, k.c1p);
    u64 u  = sub2(k.c2p, BC);
    u64 d2 = fma2(add2(Sxx, Syy), k.p9, u);
    u64 d  = mul2(d1, d2);
    float dd0, dd1; unpk(d, dd0, dd1);
    u64 rp = pk(rcpf(dd0), rcpf(dd1));
    u64 q  = mul2(n, rp);
    return fma2(q, k.nhp, k.php);
}

// Horizontal packed 3-sum of vertical sums v0 (px 0,1), v1 (px 2,3), halo hv.
#define HQ(q)                                                                 \
    float a0_##q, a1_##q, a2_##q, a3_##q;                                     \
    unpk(v0_##q, a0_##q, a1_##q);                                             \
    unpk(v1_##q, a2_##q, a3_##q);                                             \
    float lv_##q = __shfl_up_sync(0xffffffffu, a3_##q, 1);                    \
    float rv_##q = __shfl_down_sync(0xffffffffu, a0_##q, 1);                  \
    if (lane == 0)  lv_##q = (wseg == 0) ? a1_##q : hv_##q;                   \
    if (lane == 31) rv_##q = (wseg == 3) ? a2_##q : hv_##q;                   \
    u64 mid_##q = pk(a1_##q, a2_##q);                                         \
    u64 h0_##q = add2(add2(pk(lv_##q, a0_##q), v0_##q), mid_##q);             \
    u64 h1_##q = add2(add2(mid_##q, v1_##q), pk(a3_##q, rv_##q));

__device__ __forceinline__ void emit(const RowR& A, const RowR& B, const RowR& C,
                                     u64& acc, int lane, int wseg, const K& k) {
    // vertical 3-sums; squares/products as FMA chains
    u64 v0_X  = add2(add2(A.X0, B.X0), C.X0);
    u64 v1_X  = add2(add2(A.X1, B.X1), C.X1);
    u64 v0_Y  = add2(add2(A.Y0, B.Y0), C.Y0);
    u64 v1_Y  = add2(add2(A.Y1, B.Y1), C.Y1);
    u64 v0_XX = fma2(A.X0, A.X0, fma2(B.X0, B.X0, mul2(C.X0, C.X0)));
    u64 v1_XX = fma2(A.X1, A.X1, fma2(B.X1, B.X1, mul2(C.X1, C.X1)));
    u64 v0_YY = fma2(A.Y0, A.Y0, fma2(B.Y0, B.Y0, mul2(C.Y0, C.Y0)));
    u64 v1_YY = fma2(A.Y1, A.Y1, fma2(B.Y1, B.Y1, mul2(C.Y1, C.Y1)));
    u64 v0_XY = fma2(A.X0, A.Y0, fma2(B.X0, B.Y0, mul2(C.X0, C.Y0)));
    u64 v1_XY = fma2(A.X1, A.Y1, fma2(B.X1, B.Y1, mul2(C.X1, C.Y1)));

    // halo vertical sums (meaningful on lanes 0/31 only)
    float hv_X  = A.hX + B.hX + C.hX;
    float hv_Y  = A.hY + B.hY + C.hY;
    float hv_XX = fmaf(A.hX, A.hX, fmaf(B.hX, B.hX, C.hX * C.hX));
    float hv_YY = fmaf(A.hY, A.hY, fmaf(B.hY, B.hY, C.hY * C.hY));
    float hv_XY = fmaf(A.hX, A.hY, fmaf(B.hX, B.hY, C.hX * C.hY));

    HQ(X) HQ(Y) HQ(XX) HQ(YY) HQ(XY)
    acc = add2(acc, ssim2(h0_X, h0_Y, h0_XX, h0_YY, h0_XY, k));
    acc = add2(acc, ssim2(h1_X, h1_Y, h1_XX, h1_YY, h1_XY, k));
}

__global__ __launch_bounds__(128, 6)
void ssim_main(const float* __restrict__ x, const float* __restrict__ y,
               float* __restrict__ out) {
    const int tid   = threadIdx.x;
    const int lane  = tid & 31;
    const int wseg  = tid >> 5;                 // 0..3, 128-col segment
    const int plane = blockIdx.y;
    const int r0    = blockIdx.x * RPB;

    const int segbase = wseg * 128;
    const int base    = segbase + lane * 4;
    const float* __restrict__ xp = x + (size_t)plane * H * W;
    const float* __restrict__ yp = y + (size_t)plane * H * W;

    const int  hcol   = (lane == 0) ? ((wseg == 0) ? 1 : segbase - 1)
                                    : ((wseg == 3) ? 510 : segbase + 128);
    const bool doHalo = (lane == 0) || (lane == 31);

    K k;
    k.twop = pk(2.0f, 2.0f);
    k.n2p  = pk(-2.0f, -2.0f);
    k.p18  = pk(18.0f, 18.0f);
    k.p9   = pk(9.0f, 9.0f);
    k.c1p  = pk(0.0081f, 0.0081f);   // 81*C1
    k.c2p  = pk(0.0729f, 0.0729f);   // 81*C2
    k.nhp  = pk(-0.5f, -0.5f);
    k.php  = pk(0.5f, 0.5f);

    // ---- pipelined 4-buffer ring: load row r+2 before emitting row r ----
    RowR b0, b1, b2, b3;
    load_row(b0, xp, yp, (r0 == 0) ? 1 : (r0 - 1), base, hcol, doHalo);
    load_row(b1, xp, yp, r0,     base, hcol, doHalo);
    load_row(b2, xp, yp, r0 + 1, base, hcol, doHalo);

    u64 acc0 = pk(0.0f, 0.0f), acc1 = pk(0.0f, 0.0f);
    #pragma unroll 1   // rolled: hot body fits L1.5 I$ (R9 finding)
    for (int j = 0; j < RPB; j += 4) {
        const int rr = r0 + j;
        load_row(b3, xp, yp, refl_hi(rr + 2), base, hcol, doHalo);
        emit(b0, b1, b2, acc0, lane, wseg, k);                 // row rr
        load_row(b0, xp, yp, refl_hi(rr + 3), base, hcol, doHalo);
        emit(b1, b2, b3, acc1, lane, wseg, k);                 // row rr+1
        load_row(b1, xp, yp, refl_hi(rr + 4), base, hcol, doHalo);
        emit(b2, b3, b0, acc0, lane, wseg, k);                 // row rr+2
        load_row(b2, xp, yp, refl_hi(rr + 5), base, hcol, doHalo);
        emit(b3, b0, b1, acc1, lane, wseg, k);                 // row rr+3
    }

    // ---- block reduction ----
    u64 acc = add2(acc0, acc1);
    float alo, ahi; unpk(acc, alo, ahi);
    float accf = alo + ahi;
    #pragma unroll
    for (int o = 16; o > 0; o >>= 1)
        accf += __shfl_xor_sync(0xffffffffu, accf, o);

    __shared__ float wsum[4];
    __shared__ int   last_flag;
    if (lane == 0) wsum[wseg] = accf;
    __syncthreads();

    if (tid == 0) {
        float p = wsum[0] + wsum[1] + wsum[2] + wsum[3];
        g_partials[blockIdx.y * gridDim.x + blockIdx.x] = p;
        __threadfence();
        unsigned t = atomicAdd(&g_count, 1u);
        last_flag = (t == NBLOCKS - 1);
    }
    __syncthreads();

    if (last_flag) {
        double s = 0.0;
        for (int i = tid; i < NBLOCKS; i += 128)
            s += (double)__ldcg(&g_partials[i]);
        #pragma unroll
        for (int o = 16; o > 0; o >>= 1)
            s += __shfl_xor_sync(0xffffffffu, s, o);
        __shared__ double dsum[4];
        if (lane == 0) dsum[wseg] = s;
        __syncthreads();
        if (tid == 0) {
            double total = dsum[0] + dsum[1] + dsum[2] + dsum[3];
            out[0] = (float)(total / (double)((size_t)PLANES * H * W));
            g_count = 0;  // reset for next graph replay
        }
    }
}

extern "C" void kernel_launch(void* const* d_in, const int* in_sizes, int n_in,
                              void* d_out, int out_size) {
    const float* x = (const float*)d_in[0];
    const float* y = (const float*)d_in[1];
    float* out = (float*)d_out;

    dim3 grid(BLOCKS_X, PLANES);
    ssim_main<<<grid, 128>>>(x, y, out);
}

// round 17
// speedup vs baseline: 1.2715x; 1.0376x over previous
#include <cuda_runtime.h>
#include <cstdint>

// SSIM loss, NCHW (32,3,512,512) fp32, 3x3 box, reflect pad 1, scalar mean.
// R16: byte-identical to R9 (best, 59.9us) except ONE change: the lane-0/31
// horizontal fixup drops its redundant inner select. The halo load column is
// already reflection-adjusted (wseg0/lane0 loads col 1 == its own a1;
// wseg3/lane31 loads col 510 == its own a2), so hv IS the correct edge value
// unconditionally: 10 fewer SEL alu-ops per row, nothing else touched.

#define H 512
#define W 512
#define PLANES (32 * 3)
#define RPB 32
#define BLOCKS_X (H / RPB)           // 16
#define NBLOCKS (BLOCKS_X * PLANES)  // 1536

typedef unsigned long long u64;

__device__ float g_partials[NBLOCKS];
__device__ unsigned int g_count = 0;

__device__ __forceinline__ u64 pk(float lo, float hi) {
    u64 r; asm("mov.b64 %0, {%1, %2};" : "=l"(r) : "f"(lo), "f"(hi)); return r;
}
__device__ __forceinline__ void unpk(u64 v, float& lo, float& hi) {
    asm("mov.b64 {%0, %1}, %2;" : "=f"(lo), "=f"(hi) : "l"(v));
}
__device__ __forceinline__ u64 add2(u64 a, u64 b) {
    u64 d; asm("add.rn.f32x2 %0, %1, %2;" : "=l"(d) : "l"(a), "l"(b)); return d;
}
__device__ __forceinline__ u64 sub2(u64 a, u64 b) {
    u64 d; asm("sub.rn.f32x2 %0, %1, %2;" : "=l"(d) : "l"(a), "l"(b)); return d;
}
__device__ __forceinline__ u64 mul2(u64 a, u64 b) {
    u64 d; asm("mul.rn.f32x2 %0, %1, %2;" : "=l"(d) : "l"(a), "l"(b)); return d;
}
__device__ __forceinline__ u64 fma2(u64 a, u64 b, u64 c) {
    u64 d; asm("fma.rn.f32x2 %0, %1, %2, %3;" : "=l"(d) : "l"(a), "l"(b), "l"(c)); return d;
}
__device__ __forceinline__ float rcpf(float x) {
    float r; asm("rcp.approx.ftz.f32 %0, %1;" : "=f"(r) : "f"(x)); return r;
}

// Branch-free reflect for in-loop indices i in [2, 2H-2]
__device__ __forceinline__ int refl_hi(int i) {
    return min(i, 2 * (H - 1) - i);
}

// Raw row: packed x,y for 4 columns + halo scalars (lanes 0/31 only).
struct RowR { u64 X0, X1, Y0, Y1; float hX, hY; };

struct K { u64 twop, n2p, p18, p9, c1p, c2p, nhp, php; };

__device__ __forceinline__ void load_row(RowR& R,
                                         const float* __restrict__ xp,
                                         const float* __restrict__ yp,
                                         int rr, int base, int hcol, bool doHalo) {
    const float4 xv = *reinterpret_cast<const float4*>(xp + rr * W + base);
    const float4 yv = *reinterpret_cast<const float4*>(yp + rr * W + base);
    R.X0 = pk(xv.x, xv.y); R.X1 = pk(xv.z, xv.w);
    R.Y0 = pk(yv.x, yv.y); R.Y1 = pk(yv.z, yv.w);
    if (doHalo) {
        R.hX = __ldg(xp + rr * W + hcol);
        R.hY = __ldg(yp + rr * W + hcol);
    }
}

// SSIM on raw 3x3 window sums (packed pixel pair); /9 factors cancel:
//   n/d = (2A+81C1)(18 Sxy - 2A + 81C2) / ((B+C+81C1)(9(Sxx+Syy)-B-C+81C2))
__device__ __forceinline__ u64 ssim2(u64 Sx, u64 Sy, u64 Sxx, u64 Syy, u64 Sxy,
                                     const K& k) {
    u64 A  = mul2(Sx, Sy);
    u64 B  = mul2(Sx, Sx);
    u64 C  = mul2(Sy, Sy);
    u64 n1 = fma2(A, k.twop, k.c1p);
    u64 t  = fma2(A, k.n2p,  k.c2p);
    u64 n2 = fma2(Sxy, k.p18, t);
    u64 n  = mul2(n1, n2);
    u64 BC = add2(B, C);
    u64 d1 = add2(BC, k.c1p);
    u64 u  = sub2(k.c2p, BC);
    u64 d2 = fma2(add2(Sxx, Syy), k.p9, u);
    u64 d  = mul2(d1, d2);
    float dd0, dd1; unpk(d, dd0, dd1);
    u64 rp = pk(rcpf(dd0), rcpf(dd1));
    u64 q  = mul2(n, rp);
    return fma2(q, k.nhp, k.php);
}

// Horizontal packed 3-sum of vertical sums v0 (px 0,1), v1 (px 2,3), halo hv.
// hv is ALWAYS the correct edge value for lanes 0/31 (its load column already
// carries the image-edge reflection), so the fixup is a single SEL each.
#define HQ(q)                                                                 \
    float a0_##q, a1_##q, a2_##q, a3_##q;                                     \
    unpk(v0_##q, a0_##q, a1_##q);                                             \
    unpk(v1_##q, a2_##q, a3_##q);                                             \
    float lv_##q = __shfl_up_sync(0xffffffffu, a3_##q, 1);                    \
    float rv_##q = __shfl_down_sync(0xffffffffu, a0_##q, 1);                  \
    if (lane == 0)  lv_##q = hv_##q;                                          \
    if (lane == 31) rv_##q = hv_##q;                                          \
    u64 mid_##q = pk(a1_##q, a2_##q);                                         \
    u64 h0_##q = add2(add2(pk(lv_##q, a0_##q), v0_##q), mid_##q);             \
    u64 h1_##q = add2(add2(mid_##q, v1_##q), pk(a3_##q, rv_##q));

__device__ __forceinline__ void emit(const RowR& A, const RowR& B, const RowR& C,
                                     u64& acc, int lane, const K& k) {
    // vertical 3-sums; squares/products as FMA chains
    u64 v0_X  = add2(add2(A.X0, B.X0), C.X0);
    u64 v1_X  = add2(add2(A.X1, B.X1), C.X1);
    u64 v0_Y  = add2(add2(A.Y0, B.Y0), C.Y0);
    u64 v1_Y  = add2(add2(A.Y1, B.Y1), C.Y1);
    u64 v0_XX = fma2(A.X0, A.X0, fma2(B.X0, B.X0, mul2(C.X0, C.X0)));
    u64 v1_XX = fma2(A.X1, A.X1, fma2(B.X1, B.X1, mul2(C.X1, C.X1)));
    u64 v0_YY = fma2(A.Y0, A.Y0, fma2(B.Y0, B.Y0, mul2(C.Y0, C.Y0)));
    u64 v1_YY = fma2(A.Y1, A.Y1, fma2(B.Y1, B.Y1, mul2(C.Y1, C.Y1)));
    u64 v0_XY = fma2(A.X0, A.Y0, fma2(B.X0, B.Y0, mul2(C.X0, C.Y0)));
    u64 v1_XY = fma2(A.X1, A.Y1, fma2(B.X1, B.Y1, mul2(C.X1, C.Y1)));

    // halo vertical sums (meaningful on lanes 0/31 only)
    float hv_X  = A.hX + B.hX + C.hX;
    float hv_Y  = A.hY + B.hY + C.hY;
    float hv_XX = fmaf(A.hX, A.hX, fmaf(B.hX, B.hX, C.hX * C.hX));
    float hv_YY = fmaf(A.hY, A.hY, fmaf(B.hY, B.hY, C.hY * C.hY));
    float hv_XY = fmaf(A.hX, A.hY, fmaf(B.hX, B.hY, C.hX * C.hY));

    HQ(X) HQ(Y) HQ(XX) HQ(YY) HQ(XY)
    acc = add2(acc, ssim2(h0_X, h0_Y, h0_XX, h0_YY, h0_XY, k));
    acc = add2(acc, ssim2(h1_X, h1_Y, h1_XX, h1_YY, h1_XY, k));
}

__global__ __launch_bounds__(128, 6)
void ssim_main(const float* __restrict__ x, const float* __restrict__ y,
               float* __restrict__ out) {
    const int tid   = threadIdx.x;
    const int lane  = tid & 31;
    const int wseg  = tid >> 5;                 // 0..3, 128-col segment
    const int plane = blockIdx.y;
    const int r0    = blockIdx.x * RPB;

    const int segbase = wseg * 128;
    const int base    = segbase + lane * 4;
    const float* __restrict__ xp = x + (size_t)plane * H * W;
    const float* __restrict__ yp = y + (size_t)plane * H * W;

    // halo column with image-edge reflection PRE-APPLIED:
    // wseg0/lane0 -> col 1 (== its own col-1 value), wseg3/lane31 -> col 510.
    const int  hcol   = (lane == 0) ? ((wseg == 0) ? 1 : segbase - 1)
                                    : ((wseg == 3) ? 510 : segbase + 128);
    const bool doHalo = (lane == 0) || (lane == 31);

    K k;
    k.twop = pk(2.0f, 2.0f);
    k.n2p  = pk(-2.0f, -2.0f);
    k.p18  = pk(18.0f, 18.0f);
    k.p9   = pk(9.0f, 9.0f);
    k.c1p  = pk(0.0081f, 0.0081f);   // 81*C1
    k.c2p  = pk(0.0729f, 0.0729f);   // 81*C2
    k.nhp  = pk(-0.5f, -0.5f);
    k.php  = pk(0.5f, 0.5f);

    // ---- pipelined 4-buffer ring: load row r+2 before emitting row r ----
    RowR b0, b1, b2, b3;
    load_row(b0, xp, yp, (r0 == 0) ? 1 : (r0 - 1), base, hcol, doHalo);
    load_row(b1, xp, yp, r0,     base, hcol, doHalo);
    load_row(b2, xp, yp, r0 + 1, base, hcol, doHalo);

    u64 acc0 = pk(0.0f, 0.0f), acc1 = pk(0.0f, 0.0f);
    #pragma unroll 1   // rolled: hot body fits L1.5 I$ (R9 finding)
    for (int j = 0; j < RPB; j += 4) {
        const int rr = r0 + j;
        load_row(b3, xp, yp, refl_hi(rr + 2), base, hcol, doHalo);
        emit(b0, b1, b2, acc0, lane, k);                 // row rr
        load_row(b0, xp, yp, refl_hi(rr + 3), base, hcol, doHalo);
        emit(b1, b2, b3, acc1, lane, k);                 // row rr+1
        load_row(b1, xp, yp, refl_hi(rr + 4), base, hcol, doHalo);
        emit(b2, b3, b0, acc0, lane, k);                 // row rr+2
        load_row(b2, xp, yp, refl_hi(rr + 5), base, hcol, doHalo);
        emit(b3, b0, b1, acc1, lane, k);                 // row rr+3
    }

    // ---- block reduction ----
    u64 acc = add2(acc0, acc1);
    float alo, ahi; unpk(acc, alo, ahi);
    float accf = alo + ahi;
    #pragma unroll
    for (int o = 16; o > 0; o >>= 1)
        accf += __shfl_xor_sync(0xffffffffu, accf, o);

    __shared__ float wsum[4];
    __shared__ int   last_flag;
    if (lane == 0) wsum[wseg] = accf;
    __syncthreads();

    if (tid == 0) {
        float p = wsum[0] + wsum[1] + wsum[2] + wsum[3];
        g_partials[blockIdx.y * gridDim.x + blockIdx.x] = p;
        __threadfence();
        unsigned t = atomicAdd(&g_count, 1u);
        last_flag = (t == NBLOCKS - 1);
    }
    __syncthreads();

    if (last_flag) {
        double s = 0.0;
        for (int i = tid; i < NBLOCKS; i += 128)
            s += (double)__ldcg(&g_partials[i]);
        #pragma unroll
        for (int o = 16; o > 0; o >>= 1)
            s += __shfl_xor_sync(0xffffffffu, s, o);
        __shared__ double dsum[4];
        if (lane == 0) dsum[wseg] = s;
        __syncthreads();
        if (tid == 0) {
            double total = dsum[0] + dsum[1] + dsum[2] + dsum[3];
            out[0] = (float)(total / (double)((size_t)PLANES * H * W));
            g_count = 0;  // reset for next graph replay
        }
    }
}

extern "C" void kernel_launch(void* const* d_in, const int* in_sizes, int n_in,
                              void* d_out, int out_size) {
    const float* x = (const float*)d_in[0];
    const float* y = (const float*)d_in[1];
    float* out = (float*)d_out;

    dim3 grid(BLOCKS_X, PLANES);
    ssim_main<<<grid, 128>>>(x, y, out);
}